// round 17
// baseline (speedup 1.0000x reference)
#include <cuda_runtime.h>
#include <cuda_bf16.h>
#include <cstdint>

// ---------------------------------------------------------------------------
// NonLinearConv2d via sparse theta-compaction + anchored smem LUT.
// Round 17: LPT-balanced oc grouping. prep2 ranks the 64 ocs by active count
// and serpentine-assigns them into 8 groups x 8 slots (long+short paired per
// 2-oc subgroup), so every CTA and every 128-thread subgroup has ~equal work.
// Hot loop and numerics identical to R16 (T_DROP=1.30, rel_err 5.52e-4 det.).
// ---------------------------------------------------------------------------

#define TN       1024
#define APRON    136
#define TABSZ    (TN + APRON)        // 1160
#define SCALE    682.0f              // 1023 / 1.5
#define M2       12582912.0f         // 1.5 * 2^23
#define T_DROP   1.30f
#define B_       16
#define CIN_     32
#define HH       32
#define WW       32
#define OC_      64
#define OCQ      8                   // output channels per CTA
#define RT       4                   // pixel rows per CTA
#define NTHREADS 512
#define XROW     40                  // plane row stride (floats); interior at col 4
#define XPLANE   ((RT + 2) * XROW)   // 240
#define XPAD_OFF (CIN_ * XPLANE * 4) // byte offset of xpad after xs (30720)
#define MAXE     48                  // per-oc active-list capacity

__device__ float2 tabG[TABSZ];
__device__ __align__(16) float2 listsG[OC_][MAXE];
__device__ int    cntsG[OC_];
__device__ int    ocmapG[8][8];      // [group][slot] -> oc id (LPT-balanced)

struct __align__(16) Smem {
    float2 tab[TABSZ];                       //  9280 B
    float  xs[CIN_ * XPLANE];                // 30720 B (16B-aligned rows)
    float  xpad[272];                        //  1088 B (zero pad for dummies)
    __align__(16) float2 lists[OCQ][MAXE];   //  3072 B
    int    cnts[OCQ];                        //    32 B
    int    ocids[OCQ];                       //    32 B
};                                           // ~43.3 KB -> 4 CTAs/SM

__device__ __forceinline__ float gfun(float u) {
    float a1 = u * (1.0f / 0.075f);
    float a2 = (u - 0.1f) * (1.0f / 0.075f);
    a1 = fminf(fmaxf(a1, -50.0f), 50.0f);
    a2 = fminf(fmaxf(a2, -50.0f), 50.0f);
    float s1 = log1pf(expf(a1));
    float s2 = log1pf(expf(a2));
    return s1 * s1 - s2 * s2;
}

// ---- Pre-kernel 1: table + per-oc compacted lists (R16 structure).
__global__ __launch_bounds__(256)
void prep_kernel(const float* __restrict__ theta) {
    const int tid  = threadIdx.x;
    const int lane = tid & 31;
    const int wid  = tid >> 5;

    if (blockIdx.x < 8) {
        int i = blockIdx.x * 145 + tid;
        if (tid < 145 && i < TABSZ) {
            if (i < APRON) {
                tabG[i] = make_float2(0.0f, 0.0f);
            } else {
                int iz = i - APRON;
                int im = (iz > 0) ? iz - 1 : 0;
                int ip = (iz < TN - 1) ? iz + 1 : TN - 1;
                const float hstep = 1.5f / 1023.0f;
                float g0 = gfun(fmaf((float)iz, hstep, -1.5f));
                float gm = gfun(fmaf((float)im, hstep, -1.5f));
                float gp = gfun(fmaf((float)ip, hstep, -1.5f));
                float s  = (gp - gm) / (float)(ip - im);
                tabG[i] = make_float2(fmaf(-(float)iz, s, g0), s);
            }
        }
    } else {
        int o = (blockIdx.x - 8) * 8 + wid;      // 64 warps, 1 list each
        const float* tp = theta + (size_t)o * (CIN_ * 9);
        float tv[9];
        #pragma unroll
        for (int ch = 0; ch < 9; ch++)           // 9 independent LDGs
            tv[ch] = tp[ch * 32 + lane];
        int cnt = 0;
        #pragma unroll
        for (int ch = 0; ch < 9; ch++) {
            int idx = ch * 32 + lane;            // ci*9 + k
            float t = fmaxf(tv[ch], 1.0f);
            bool act = (t < T_DROP);
            unsigned bal = __ballot_sync(0xFFFFFFFFu, act);
            if (act) {
                int pos = cnt + __popc(bal & ((1u << lane) - 1u));
                int ci = idx / 9, k = idx - ci * 9;
                int kh = k / 3, kw = k - kh * 3;
                int off = (ci * XPLANE + kh * XROW + kw) * 4;
                float ttm = fmaf(-SCALE, t, 1023.0f);   // 682*(1.5 - t)
                listsG[o][pos] = make_float2(ttm, __int_as_float(off));
            }
            cnt += __popc(bal);
        }
        int npad = (-cnt) & 7;                  // pad to multiple of 8
        if (lane < npad)
            listsG[o][cnt + lane] = make_float2(-64.0f, __int_as_float(XPAD_OFF));
        cnt += npad;
        if (lane == 0) cntsG[o] = cnt;
    }
}

// ---- Pre-kernel 2: LPT-balance ocs into 8 groups x 8 slots.
// rank r by cnt desc (ties by id); serpentine: group = r%8 fwd/rev by round;
// slot position pairs round j with round 7-j into the same 2-oc subgroup.
__global__ void prep2_kernel() {
    int o  = threadIdx.x;                        // 0..63
    int my = cntsG[o];
    int r  = 0;
    #pragma unroll 8
    for (int j = 0; j < OC_; j++) {
        int cj = cntsG[j];
        r += (cj > my) || (cj == my && j < o);
    }
    int round = r >> 3;
    int g = (round & 1) ? (7 - (r & 7)) : (r & 7);
    int pos = (round < 4) ? (round * 2) : ((7 - round) * 2 + 1);
    ocmapG[g][pos] = o;
}

__global__ __launch_bounds__(NTHREADS, 4)
void nlconv_kernel(const float* __restrict__ x,
                   float* __restrict__ out) {
    extern __shared__ char smraw[];
    Smem* sm = (Smem*)smraw;

    const int tid = threadIdx.x;
    const int b   = blockIdx.y;
    const int gz  = blockIdx.z;                 // balanced group id

    const int h0  = blockIdx.x * RT;

    // ---- Prologue ---------------------------------------------------------
    for (int i = tid; i < TABSZ; i += NTHREADS) sm->tab[i] = tabG[i];
    if (tid < 272) sm->xpad[tid] = 0.0f;
    if (tid < OCQ) {
        int oc = ocmapG[gz][tid];
        sm->ocids[tid] = oc;
        sm->cnts[tid]  = cntsG[oc];
    }
    for (int i = tid; i < OCQ * MAXE; i += NTHREADS) {
        int p = i / MAXE, e = i - p * MAXE;
        sm->lists[p][e] = listsG[ocmapG[gz][p]][e];
    }

    // zero halo columns (col 3 = left pad, col 36 = right pad), 6 rows x 32 ci
    if (tid < 384) {
        int ci  = tid / 12;
        int rem = tid - ci * 12;
        int rr  = rem >> 1;
        int col = (rem & 1) ? 36 : 3;
        sm->xs[ci * XPLANE + rr * XROW + col] = 0.0f;
    }

    // interior: 32 ci x 6 rows x 8 float4 = 1536 chunks, 3 per thread.
    const float4* xb4 = (const float4*)(x + (size_t)b * CIN_ * HH * WW);
    #pragma unroll
    for (int k = 0; k < 3; k++) {
        int chunk = tid + k * NTHREADS;          // < 1536
        int ci  = chunk / 48;
        int rem = chunk - ci * 48;
        int rr  = rem >> 3;
        int q   = rem & 7;
        int gh  = h0 + rr - 1;
        float4 v = make_float4(0.0f, 0.0f, 0.0f, 0.0f);
        if (gh >= 0 && gh < HH)
            v = xb4[ci * 256 + gh * 8 + q];
        v.x *= SCALE; v.y *= SCALE; v.z *= SCALE; v.w *= SCALE;
        *(float4*)&sm->xs[ci * XPLANE + rr * XROW + 4 + q * 4] = v;
    }
    __syncthreads();

    // ---- Main: per-slot compacted accumulation ----------------------------
    // 512 threads = 4 subgroups x 128 pixels; og, r warp-uniform; 2 slots each
    // (slot pairing long+short by prep2 -> subgroup work ~equal).
    const int og  = tid >> 7;                   // 0..3
    const int pix = tid & 127;
    const int r   = pix >> 5;                   // 0..3 row in tile
    const int c   = pix & 31;                   // 0..31 col
    const int h   = h0 + r;

    uint32_t xbase = (uint32_t)__cvta_generic_to_shared(sm->xs) + (r * XROW + c + 3) * 4;
    uint32_t Kc    = (uint32_t)__cvta_generic_to_shared(sm->tab) + APRON * 8 - 0x5A000000u;

#define PROC(TT, OFFF) {                                                      \
        uint32_t xa = xbase + (uint32_t)__float_as_int(OFFF);                 \
        float xv;                                                             \
        asm("ld.shared.f32 %0, [%1];" : "=f"(xv) : "r"(xa));                  \
        float z = xv + (TT);                                                  \
        float y = z + M2;                                                     \
        uint32_t ga = (__float_as_uint(y) << 3) + Kc;                         \
        float ex, ey;                                                         \
        asm("ld.shared.v2.f32 {%0,%1}, [%2];" : "=f"(ex), "=f"(ey) : "r"(ga));\
        a += fmaf(z, ey, ex);                                                 \
    }

    #pragma unroll 1
    for (int oi = 0; oi < 2; oi++) {
        const int p   = og * 2 + oi;            // slot in this CTA
        const int cnt = sm->cnts[p];
        const float4* lp4 = (const float4*)sm->lists[p];
        float a = 0.0f;
        #pragma unroll 1
        for (int j = 0; j < cnt; j += 8) {
            float4 q0 = lp4[(j >> 1) + 0];
            float4 q1 = lp4[(j >> 1) + 1];
            float4 q2 = lp4[(j >> 1) + 2];
            float4 q3 = lp4[(j >> 1) + 3];
            PROC(q0.x, q0.y) PROC(q0.z, q0.w)
            PROC(q1.x, q1.y) PROC(q1.z, q1.w)
            PROC(q2.x, q2.y) PROC(q2.z, q2.w)
            PROC(q3.x, q3.y) PROC(q3.z, q3.w)
        }
        int ocs = sm->ocids[p];
        float* op = out + ((size_t)(b * OC_ + ocs) * HH + h) * WW + c;
        *op = 0.0005625f * a;
    }
#undef PROC
}

extern "C" void kernel_launch(void* const* d_in, const int* in_sizes, int n_in,
                              void* d_out, int out_size) {
    const float* x     = (const float*)d_in[0];
    const float* theta = (const float*)d_in[1];
    float*       out   = (float*)d_out;
    int smem = (int)sizeof(Smem);
    cudaFuncSetAttribute(nlconv_kernel, cudaFuncAttributeMaxDynamicSharedMemorySize, smem);
    prep_kernel<<<16, 256>>>(theta);
    prep2_kernel<<<1, 64>>>();
    dim3 grid(HH / RT, B_, OC_ / OCQ);   // 8 x 16 x 8 = 1024 CTAs
    nlconv_kernel<<<grid, NTHREADS, smem>>>(x, out);
}